// round 4
// baseline (speedup 1.0000x reference)
#include <cuda_runtime.h>
#include <math.h>

// QuanvolutionHybrid, fully collapsed:
// Only feats[:,0] (patch 0, wire0 <Z>) feeds the FC stage. The post-embedding
// circuit is a FIXED 16x16 unitary U, and ez = Tr(M rho), M = U^dag Z0 U,
// rho = tensor_w [ (I + cos(th_w) Z - sin(th_w) Y)/2 ]  (RX embedding).
// => ez = sum_{p in {I,Z,Y}^4} T[p] prod_w v_w[p_w],  v = (1, cos, -sin).
// Kernel 1 (1 block): build T[81] once. Kernel 2: per-sample 80-FMA contraction
// + 1-qubit FC circuit + Linear(1,10) + log_softmax. No shuffles in the hot path.

#define SHX(v, m) __shfl_xor_sync(0xffffffffu, (v), (m))

__device__ float g_T[81];

__device__ __forceinline__ void rot_mat_fast(float phi, float theta, float omega, float4* m) {
    // PennyLane Rot(phi,theta,omega) = RZ(omega) RY(theta) RZ(phi)
    float ct, st, ca, sa, cb, sb;
    __sincosf(0.5f * theta, &st, &ct);
    __sincosf(0.5f * (phi + omega), &sa, &ca);
    __sincosf(0.5f * (phi - omega), &sb, &cb);
    m[0] = make_float4( ct * ca, -ct * sa, -st * cb, -st * sb);  // m00, m01
    m[1] = make_float4( st * cb, -st * sb,  ct * ca,  ct * sa);  // m10, m11
}

// ---------------- Kernel 1: build T[81] ----------------
// 256 threads: thread = col*16 + k holds amplitude k of U|col>.
// Wire w corresponds to amp-index bit (8 >> w) (wire0 = MSB).
__global__ void __launch_bounds__(256)
build_T_kernel(const float* __restrict__ wq)   // [2,2,4,3]
{
    __shared__ float4 qm[16][2];
    __shared__ float ur[16][17], ui[16][17];   // U[k][col]
    __shared__ float mr[16][17], mi[16][17];   // M[i][j]

    const int tid = threadIdx.x;
    if (tid < 16) {
        const float* p = wq + tid * 3;          // gate ((app*2+l)*4+w)
        rot_mat_fast(p[0], p[1], p[2], qm[tid]);
    }
    __syncthreads();

    const int col = tid >> 4;
    const int k   = tid & 15;
    float ar = (k == col) ? 1.f : 0.f, ai = 0.f;

    // StronglyEntanglingLayers: 2 apps x 2 layers (shfl groups of 16 lanes)
#pragma unroll
    for (int app = 0; app < 2; app++) {
#pragma unroll
        for (int l = 0; l < 2; l++) {
#pragma unroll
            for (int w = 0; w < 4; w++) {
                const float4 mA = qm[(app * 2 + l) * 4 + w][0];
                const float4 mB = qm[(app * 2 + l) * 4 + w][1];
                const int mu = 8 >> w;
                float pr = SHX(ar, mu), pi = SHX(ai, mu);
                const bool bit = (k & mu) != 0;
                float c0r = bit ? mB.z : mA.x, c0i = bit ? mB.w : mA.y; // coeff on own amp
                float c1r = bit ? mB.x : mA.z, c1i = bit ? mB.y : mA.w; // coeff on partner
                float nr = c0r * ar - c0i * ai + c1r * pr - c1i * pi;
                float ni = c0r * ai + c0i * ar + c1r * pi + c1i * pr;
                ar = nr; ai = ni;
            }
            const int r = (l == 0) ? 1 : 2;
#pragma unroll
            for (int w = 0; w < 4; w++) {
                const int cmask = 8 >> w;
                const int tmask = 8 >> ((w + r) & 3);
                float pr = SHX(ar, tmask), pi = SHX(ai, tmask);
                const bool c = (k & cmask) != 0;
                ar = c ? pr : ar;
                ai = c ? pi : ai;
            }
        }
    }
    ur[k][col] = ar;
    ui[k][col] = ai;
    __syncthreads();

    // M_ij = sum_k z_k conj(U_ki) U_kj , z_k = +1 (k<8) else -1
    {
        const int i = tid >> 4, j = tid & 15;
        float sr = 0.f, sim = 0.f;
#pragma unroll
        for (int kk = 0; kk < 16; kk++) {
            const float z = (kk < 8) ? 1.f : -1.f;
            float air = ur[kk][i], aii = ui[kk][i];
            float ajr = ur[kk][j], aji = ui[kk][j];
            sr  += z * (air * ajr + aii * aji);
            sim += z * (air * aji - aii * ajr);
        }
        mr[i][j] = sr;
        mi[i][j] = sim;
    }
    __syncthreads();

    // T[p] = (1/16) Re( i^{nY} * sum_i sgn_p(i) M_{i, i^m} )
    //   m  = OR of (8>>w) for p_w == Y ;  sgn flips on Z and Y wires' bits.
    if (tid < 81) {
        const int p0 = tid / 27, p1 = (tid / 9) % 3, p2 = (tid / 3) % 3, p3 = tid % 3;
        const int pw[4] = { p0, p1, p2, p3 };
        int m = 0, sm = 0, nY = 0;
#pragma unroll
        for (int w = 0; w < 4; w++) {
            const int mu = 8 >> w;
            if (pw[w] == 2) { m |= mu; nY++; }
            if (pw[w] >= 1) sm |= mu;
        }
        float accr = 0.f, acci = 0.f;
#pragma unroll
        for (int i = 0; i < 16; i++) {
            const int j = i ^ m;
            const float sg = (__popc(i & sm) & 1) ? -1.f : 1.f;
            accr += sg * mr[i][j];
            acci += sg * mi[i][j];
        }
        float res;
        switch (nY & 3) {
            case 0:  res =  accr; break;
            case 1:  res = -acci; break;
            case 2:  res = -accr; break;
            default: res =  acci; break;
        }
        g_T[tid] = res * (1.f / 16.f);
    }
}

// ---------------- Kernel 2: per-sample evaluation ----------------
__global__ void __launch_bounds__(64)
eval_kernel(const float* __restrict__ x,
            const float* __restrict__ wfc,   // [3,3,1,3]
            const float* __restrict__ Wout,  // [10,1]
            const float* __restrict__ bout,  // [10]
            float* __restrict__ out,         // [B,10]
            int B)
{
    __shared__ float  ts[81];
    __shared__ float4 fm[9][2];
    __shared__ float  wo[10], bo[10];

    const int tid = threadIdx.x;
    const int b = blockIdx.x * 64 + tid;
    const int scl = (b < B) ? b : (B - 1);

    // Global loads first: pixels overlap prologue latency.
    const float* xb = x + (size_t)scl * 784;
    const float2 p01 = *(const float2*)(xb);        // th0, th1
    const float2 p23 = *(const float2*)(xb + 28);   // th2, th3

    // Prologue: stage T, fc gate matrices, Wout/bout.
    ts[tid] = g_T[tid < 81 ? tid : 0];
    if (tid < 17) ts[64 + tid] = g_T[64 + tid];
    else if (tid < 26) {
        const float* p = wfc + (tid - 17) * 3;      // gate (app*3+l)
        rot_mat_fast(p[0], p[1], p[2], fm[tid - 17]);
    } else if (tid == 26) {
#pragma unroll
        for (int kk = 0; kk < 10; kk++) wo[kk] = __ldg(Wout + kk);
    } else if (tid == 27) {
#pragma unroll
        for (int kk = 0; kk < 10; kk++) bo[kk] = __ldg(bout + kk);
    }

    float c0, s0, c1, s1, c2, s2, c3, s3;
    __sincosf(p01.x, &s0, &c0);   // full angles (Bloch vector uses cos, sin)
    __sincosf(p01.y, &s1, &c1);
    __sincosf(p23.x, &s2, &c2);
    __sincosf(p23.y, &s3, &c3);

    __syncthreads();

    // ez = T contracted with v_w = (1, cos th_w, -sin th_w), wire order p0..p3
    float r27[27];
#pragma unroll
    for (int a = 0; a < 27; a++)
        r27[a] = ts[3 * a] + c3 * ts[3 * a + 1] - s3 * ts[3 * a + 2];
    float r9[9];
#pragma unroll
    for (int a = 0; a < 9; a++)
        r9[a] = r27[3 * a] + c2 * r27[3 * a + 1] - s2 * r27[3 * a + 2];
    float r3[3];
#pragma unroll
    for (int a = 0; a < 3; a++)
        r3[a] = r9[3 * a] + c1 * r9[3 * a + 1] - s1 * r9[3 * a + 2];
    const float ez = r3[0] + c0 * r3[1] - s0 * r3[2];

    // 1-qubit FC circuit: RX(ez)|0>, then 9 shared Rot gates
    float cf, sf;
    __sincosf(0.5f * ez, &sf, &cf);
    float a0r = cf, a0i = 0.f, a1r = 0.f, a1i = -sf;
#pragma unroll
    for (int g = 0; g < 9; g++) {
        const float4 mA = fm[g][0];
        const float4 mB = fm[g][1];
        float n0r = mA.x * a0r - mA.y * a0i + mA.z * a1r - mA.w * a1i;
        float n0i = mA.x * a0i + mA.y * a0r + mA.z * a1i + mA.w * a1r;
        float n1r = mB.x * a0r - mB.y * a0i + mB.z * a1r - mB.w * a1i;
        float n1i = mB.x * a0i + mB.y * a0r + mB.z * a1i + mB.w * a1r;
        a0r = n0r; a0i = n0i; a1r = n1r; a1i = n1i;
    }
    const float q = (a0r * a0r + a0i * a0i) - (a1r * a1r + a1i * a1i);

    // Linear(1,10) + log_softmax
    float lg[10], mx = -1e30f;
#pragma unroll
    for (int k = 0; k < 10; k++) {
        lg[k] = fmaf(q, wo[k], bo[k]);
        mx = fmaxf(mx, lg[k]);
    }
    float se = 0.f;
#pragma unroll
    for (int k = 0; k < 10; k++) se += __expf(lg[k] - mx);
    const float off = mx + __logf(se);

    if (b < B) {
        float2* ob = (float2*)(out + (size_t)b * 10);   // 40B rows -> 8B aligned
#pragma unroll
        for (int k = 0; k < 5; k++)
            ob[k] = make_float2(lg[2 * k] - off, lg[2 * k + 1] - off);
    }
}

extern "C" void kernel_launch(void* const* d_in, const int* in_sizes, int n_in,
                              void* d_out, int out_size) {
    const float* x    = (const float*)d_in[0];   // [B,784]
    const float* wq   = (const float*)d_in[1];   // [2,2,4,3]
    const float* wfc  = (const float*)d_in[2];   // [3,3,1,3]
    const float* Wout = (const float*)d_in[3];   // [10,1]
    const float* bout = (const float*)d_in[4];   // [10]
    float* out = (float*)d_out;                  // [B,10]

    int B = in_sizes[0] / 784;
    build_T_kernel<<<1, 256>>>(wq);
    eval_kernel<<<(B + 63) / 64, 64>>>(x, wfc, Wout, bout, out, B);
}

// round 5
// speedup vs baseline: 1.1962x; 1.1962x over previous
#include <cuda_runtime.h>
#include <math.h>

// QuanvolutionHybrid, fully collapsed, SINGLE kernel (one launch = one fixed floor).
// Only feats[:,0] (patch 0, wire0 <Z>) feeds the FC stage. The post-embedding
// circuit is a FIXED 16x16 unitary U; ez = Tr(M rho), M = U^dag Z0 U,
// rho = tensor_w [(I + cos(th_w) Z - sin(th_w) Y)/2]  (RX embedding), so
//   ez = sum_{p in {I,Z,Y}^4} T[p] prod_w v_w[p_w],  v = (1, cos, -sin).
// Each 256-thread block redundantly builds T[81] in SMEM (validated R4 math),
// then each thread evaluates one sample: 80-FMA contraction + 1-qubit FC
// circuit + Linear(1,10) + log_softmax (no max-shift needed: |logits| <= ~0.4).

#define SHX(v, m) __shfl_xor_sync(0xffffffffu, (v), (m))

__device__ __forceinline__ void rot_mat_fast(float phi, float theta, float omega, float4* m) {
    // PennyLane Rot(phi,theta,omega) = RZ(omega) RY(theta) RZ(phi)
    float ct, st, ca, sa, cb, sb;
    __sincosf(0.5f * theta, &st, &ct);
    __sincosf(0.5f * (phi + omega), &sa, &ca);
    __sincosf(0.5f * (phi - omega), &sb, &cb);
    m[0] = make_float4( ct * ca, -ct * sa, -st * cb, -st * sb);  // m00, m01
    m[1] = make_float4( st * cb, -st * sb,  ct * ca,  ct * sa);  // m10, m11
}

__global__ void __launch_bounds__(256)
quanv_fused_kernel(const float* __restrict__ x,
                   const float* __restrict__ wq,    // [2,2,4,3]
                   const float* __restrict__ wfc,   // [3,3,1,3]
                   const float* __restrict__ Wout,  // [10,1]
                   const float* __restrict__ bout,  // [10]
                   float* __restrict__ out,         // [B,10]
                   int B)
{
    __shared__ float4 qm[16][2];
    __shared__ float4 fm[9][2];
    __shared__ float  ur[16][17], ui[16][17];   // U[k][col]
    __shared__ float  mr[16][17], mi[16][17];   // M[i][j]
    __shared__ float  ts[81];
    __shared__ float  wo[10], bo[10];

    const int tid = threadIdx.x;
    const int s   = blockIdx.x * 256 + tid;
    const int scl = (s < B) ? s : (B - 1);

    // Issue sample pixel loads FIRST: cold-DRAM latency overlaps the prologue.
    const float* xb = x + (size_t)scl * 784;
    const float2 p01 = *(const float2*)(xb);        // th0, th1
    const float2 p23 = *(const float2*)(xb + 28);   // th2, th3

    // ---- prologue: gate matrices + head weights ----
    if (tid < 16) {
        const float* p = wq + tid * 3;              // gate ((app*2+l)*4+w)
        rot_mat_fast(p[0], p[1], p[2], qm[tid]);
    } else if (tid < 25) {
        const float* p = wfc + (tid - 16) * 3;      // gate (app*3+l)
        rot_mat_fast(p[0], p[1], p[2], fm[tid - 16]);
    } else if (tid == 25) {
#pragma unroll
        for (int k = 0; k < 10; k++) wo[k] = __ldg(Wout + k);
    } else if (tid == 26) {
#pragma unroll
        for (int k = 0; k < 10; k++) bo[k] = __ldg(bout + k);
    }

    // per-sample Bloch angles (full angle, not half)
    float c0, s0, c1, s1, c2, s2, c3, s3;
    __sincosf(p01.x, &s0, &c0);
    __sincosf(p01.y, &s1, &c1);
    __sincosf(p23.x, &s2, &c2);
    __sincosf(p23.y, &s3, &c3);

    __syncthreads();

    // ---- build U: thread = col*16 + k holds amp k of U|col> ----
    {
        const int col = tid >> 4;
        const int k   = tid & 15;
        float ar = (k == col) ? 1.f : 0.f, ai = 0.f;

#pragma unroll
        for (int app = 0; app < 2; app++) {
#pragma unroll
            for (int l = 0; l < 2; l++) {
#pragma unroll
                for (int w = 0; w < 4; w++) {
                    const float4 mA = qm[(app * 2 + l) * 4 + w][0];
                    const float4 mB = qm[(app * 2 + l) * 4 + w][1];
                    const int mu = 8 >> w;
                    float pr = SHX(ar, mu), pi = SHX(ai, mu);
                    const bool bit = (k & mu) != 0;
                    float c0r = bit ? mB.z : mA.x, c0i = bit ? mB.w : mA.y;
                    float c1r = bit ? mB.x : mA.z, c1i = bit ? mB.y : mA.w;
                    float nr = c0r * ar - c0i * ai + c1r * pr - c1i * pi;
                    float ni = c0r * ai + c0i * ar + c1r * pi + c1i * pr;
                    ar = nr; ai = ni;
                }
                const int r = (l == 0) ? 1 : 2;
#pragma unroll
                for (int w = 0; w < 4; w++) {
                    const int cmask = 8 >> w;
                    const int tmask = 8 >> ((w + r) & 3);
                    float pr = SHX(ar, tmask), pi = SHX(ai, tmask);
                    const bool c = (k & cmask) != 0;
                    ar = c ? pr : ar;
                    ai = c ? pi : ai;
                }
            }
        }
        ur[k][col] = ar;
        ui[k][col] = ai;
    }
    __syncthreads();

    // ---- M_ij = sum_k z_k conj(U_ki) U_kj ----
    {
        const int i = tid >> 4, j = tid & 15;
        float sr = 0.f, sim = 0.f;
#pragma unroll
        for (int kk = 0; kk < 16; kk++) {
            const float z = (kk < 8) ? 1.f : -1.f;
            float air = ur[kk][i], aii = ui[kk][i];
            float ajr = ur[kk][j], aji = ui[kk][j];
            sr  += z * (air * ajr + aii * aji);
            sim += z * (air * aji - aii * ajr);
        }
        mr[i][j] = sr;
        mi[i][j] = sim;
    }
    __syncthreads();

    // ---- T[p] = (1/16) Re( i^{nY} sum_i sgn_p(i) M_{i, i^m} ) ----
    if (tid < 81) {
        const int p0 = tid / 27, p1 = (tid / 9) % 3, p2 = (tid / 3) % 3, p3 = tid % 3;
        const int pw[4] = { p0, p1, p2, p3 };
        int m = 0, sm = 0, nY = 0;
#pragma unroll
        for (int w = 0; w < 4; w++) {
            const int mu = 8 >> w;
            if (pw[w] == 2) { m |= mu; nY++; }
            if (pw[w] >= 1) sm |= mu;
        }
        float accr = 0.f, acci = 0.f;
#pragma unroll
        for (int i = 0; i < 16; i++) {
            const int j = i ^ m;
            const float sg = (__popc(i & sm) & 1) ? -1.f : 1.f;
            accr += sg * mr[i][j];
            acci += sg * mi[i][j];
        }
        float res;
        switch (nY & 3) {
            case 0:  res =  accr; break;
            case 1:  res = -acci; break;
            case 2:  res = -accr; break;
            default: res =  acci; break;
        }
        ts[tid] = res * (1.f / 16.f);
    }
    __syncthreads();

    // ---- per-sample: ez = T x (1,c,-s)^{x4}, wire order p0..p3 ----
    float r27[27];
#pragma unroll
    for (int a = 0; a < 27; a++)
        r27[a] = ts[3 * a] + c3 * ts[3 * a + 1] - s3 * ts[3 * a + 2];
    float r9[9];
#pragma unroll
    for (int a = 0; a < 9; a++)
        r9[a] = r27[3 * a] + c2 * r27[3 * a + 1] - s2 * r27[3 * a + 2];
    float r3[3];
#pragma unroll
    for (int a = 0; a < 3; a++)
        r3[a] = r9[3 * a] + c1 * r9[3 * a + 1] - s1 * r9[3 * a + 2];
    const float ez = r3[0] + c0 * r3[1] - s0 * r3[2];

    // ---- 1-qubit FC circuit: RX(ez)|0>, then 9 shared Rot gates ----
    float cf, sf;
    __sincosf(0.5f * ez, &sf, &cf);
    float a0r = cf, a0i = 0.f, a1r = 0.f, a1i = -sf;
#pragma unroll
    for (int g = 0; g < 9; g++) {
        const float4 mA = fm[g][0];
        const float4 mB = fm[g][1];
        float n0r = mA.x * a0r - mA.y * a0i + mA.z * a1r - mA.w * a1i;
        float n0i = mA.x * a0i + mA.y * a0r + mA.z * a1i + mA.w * a1r;
        float n1r = mB.x * a0r - mB.y * a0i + mB.z * a1r - mB.w * a1i;
        float n1i = mB.x * a0i + mB.y * a0r + mB.z * a1i + mB.w * a1r;
        a0r = n0r; a0i = n0i; a1r = n1r; a1i = n1i;
    }
    const float q = (a0r * a0r + a0i * a0i) - (a1r * a1r + a1i * a1i);

    // ---- Linear(1,10) + log_softmax (|logits| <= ~0.4: no max-shift needed) ----
    float lg[10];
    float se = 0.f;
#pragma unroll
    for (int k = 0; k < 10; k++) {
        lg[k] = fmaf(q, wo[k], bo[k]);
        se += __expf(lg[k]);
    }
    const float off = __logf(se);

    if (s < B) {
        float2* ob = (float2*)(out + (size_t)s * 10);   // 40B rows -> 8B aligned
#pragma unroll
        for (int k = 0; k < 5; k++)
            ob[k] = make_float2(lg[2 * k] - off, lg[2 * k + 1] - off);
    }
}

extern "C" void kernel_launch(void* const* d_in, const int* in_sizes, int n_in,
                              void* d_out, int out_size) {
    const float* x    = (const float*)d_in[0];   // [B,784]
    const float* wq   = (const float*)d_in[1];   // [2,2,4,3]
    const float* wfc  = (const float*)d_in[2];   // [3,3,1,3]
    const float* Wout = (const float*)d_in[3];   // [10,1]
    const float* bout = (const float*)d_in[4];   // [10]
    float* out = (float*)d_out;                  // [B,10]

    int B = in_sizes[0] / 784;
    int blocks = (B + 255) / 256;
    quanv_fused_kernel<<<blocks, 256>>>(x, wq, wfc, Wout, bout, out, B);
}

// round 6
// speedup vs baseline: 1.4398x; 1.2037x over previous
#include <cuda_runtime.h>
#include <math.h>

// QuanvolutionHybrid, reduced: only feats[:,0] (patch 0, wire0 <Z>) feeds the
// FC stage. Direct 4-qubit sim, 4 threads/sample (4 amps each), with:
//  - embedding built directly as product state (no RX gate stages)
//  - each CNOT ring merged into ONE permutation-shfl stage
//  - FC circuit collapsed to q = alpha*cos(ez) + beta*sin(ez); (alpha,beta)
//    computed by a helper warp CONCURRENTLY with the gate phase
//  - softmax exps split across the 4 lanes of each sample group
// Block = 160 threads (4 sim warps = 32 samples + 1 helper warp), grid = B/32.

#define SHX(v, m)  __shfl_xor_sync(0xffffffffu, (v), (m))
#define SH4(v, l)  __shfl_sync(0xffffffffu, (v), (l), 4)
#define SH4X(v, m) __shfl_xor_sync(0xffffffffu, (v), (m), 4)

__device__ __forceinline__ void rot_mat_fast(float phi, float theta, float omega, float4* m) {
    // PennyLane Rot(phi,theta,omega) = RZ(omega) RY(theta) RZ(phi)
    float ct, st, ca, sa, cb, sb;
    __sincosf(0.5f * theta, &st, &ct);
    __sincosf(0.5f * (phi + omega), &sa, &ca);
    __sincosf(0.5f * (phi - omega), &sb, &cb);
    m[0] = make_float4( ct * ca, -ct * sa, -st * cb, -st * sb);  // m00, m01
    m[1] = make_float4( st * cb, -st * sb,  ct * ca,  ct * sa);  // m10, m11
}

// Local Rot on a pair of this thread's amps
#define ROT_LOCAL_PAIR(P, Q, mA, mB) {                                        \
    float n0r = mA.x*ar##P - mA.y*ai##P + mA.z*ar##Q - mA.w*ai##Q;            \
    float n0i = mA.x*ai##P + mA.y*ar##P + mA.z*ai##Q + mA.w*ar##Q;            \
    float n1r = mB.x*ar##P - mB.y*ai##P + mB.z*ar##Q - mB.w*ai##Q;            \
    float n1i = mB.x*ai##P + mB.y*ar##P + mB.z*ai##Q + mB.w*ar##Q;            \
    ar##P = n0r; ai##P = n0i; ar##Q = n1r; ai##Q = n1i; }

#define ROT_CROSS_AMP(K, mask) {                                              \
    float pr = SHX(ar##K, mask), pi = SHX(ai##K, mask);                       \
    float nr = csr*ar##K - csi*ai##K + cpr*pr - cpi*pi;                       \
    float ni = csr*ai##K + csi*ar##K + cpr*pi + cpi*pr;                       \
    ar##K = nr; ai##K = ni; }

// Cross-thread Rot on a lane-bit wire; BIT = this thread's wire bit
#define ROT_CROSS(mask, BIT, mA, mB) {                                        \
    float csr = (BIT) ? mB.z : mA.x, csi = (BIT) ? mB.w : mA.y;               \
    float cpr = (BIT) ? mB.x : mA.z, cpi = (BIT) ? mB.y : mA.w;               \
    ROT_CROSS_AMP(0, mask) ROT_CROSS_AMP(1, mask)                             \
    ROT_CROSS_AMP(2, mask) ROT_CROSS_AMP(3, mask) }

__device__ __forceinline__ float sel4(int k, float a0, float a1, float a2, float a3) {
    float lo = (k & 1) ? a1 : a0;
    float hi = (k & 1) ? a3 : a2;
    return (k & 2) ? hi : lo;
}

__global__ void __launch_bounds__(160)
quanv_hybrid_kernel(const float* __restrict__ x,
                    const float* __restrict__ wq,    // [2,2,4,3]
                    const float* __restrict__ wfc,   // [3,3,1,3]
                    const float* __restrict__ Wout,  // [10,1]
                    const float* __restrict__ bout,  // [10]
                    float* __restrict__ out,         // [B,10]
                    int B)
{
    __shared__ float4 qm[16][2];
    __shared__ float4 fm9[9][2];
    __shared__ float  ab[2];          // alpha, beta
    __shared__ float  wo[10], bo[10];

    const int tid = threadIdx.x;

    if (tid >= 128) {
        // ---------------- helper warp: (alpha,beta) + head weights ----------------
        const int l = tid - 128;
        float w0v = 0.f, w1v = 0.f, w2v = 0.f;
        if (l < 9) {                       // issue loads before the barrier
            const float* p = wfc + l * 3;  // gate order (app*3+l)
            w0v = p[0]; w1v = p[1]; w2v = p[2];
        } else if (l == 9) {
#pragma unroll
            for (int k = 0; k < 10; k++) wo[k] = __ldg(Wout + k);
        } else if (l == 10) {
#pragma unroll
            for (int k = 0; k < 10; k++) bo[k] = __ldg(bout + k);
        }
        __syncthreads();                   // b1 (arrive early; qm for sim warps)
        if (l < 9) rot_mat_fast(w0v, w1v, w2v, fm9[l]);
        __syncwarp();
        if (l == 0) {
            // propagate both columns of V = fm9[8]...fm9[0]
            float c0r = 1.f, c0i = 0.f, c1r = 0.f, c1i = 0.f;   // V|0>
            float d0r = 0.f, d0i = 0.f, d1r = 1.f, d1i = 0.f;   // V|1>
#pragma unroll
            for (int g = 0; g < 9; g++) {
                const float4 mA = fm9[g][0];
                const float4 mB = fm9[g][1];
                float n0r = mA.x*c0r - mA.y*c0i + mA.z*c1r - mA.w*c1i;
                float n0i = mA.x*c0i + mA.y*c0r + mA.z*c1i + mA.w*c1r;
                float n1r = mB.x*c0r - mB.y*c0i + mB.z*c1r - mB.w*c1i;
                float n1i = mB.x*c0i + mB.y*c0r + mB.z*c1i + mB.w*c1r;
                c0r = n0r; c0i = n0i; c1r = n1r; c1i = n1i;
                float m0r = mA.x*d0r - mA.y*d0i + mA.z*d1r - mA.w*d1i;
                float m0i = mA.x*d0i + mA.y*d0r + mA.z*d1i + mA.w*d1r;
                float m1r = mB.x*d0r - mB.y*d0i + mB.z*d1r - mB.w*d1i;
                float m1i = mB.x*d0i + mB.y*d0r + mB.z*d1i + mB.w*d1r;
                d0r = m0r; d0i = m0i; d1r = m1r; d1i = m1i;
            }
            // alpha = |v00|^2 - |v10|^2 ; beta = Im(v00* v01) - Im(v10* v11)
            ab[0] = (c0r*c0r + c0i*c0i) - (c1r*c1r + c1i*c1i);
            ab[1] = (c0r*d0i - c0i*d0r) - (c1r*d1i - c1i*d1r);
        }
        __syncthreads();                   // b2
        return;
    }

    // ---------------- sim warps: 4 threads per sample ----------------
    const int g = tid & 3;
    const int s = blockIdx.x * 32 + (tid >> 2);
    const int scl = (s < B) ? s : (B - 1);

    // own wire's pixel: patch 0 offsets {0,1,28,29}
    const float pix = x[(size_t)scl * 784 + ((g & 1) + 28 * (g >> 1))];

    // qm build (warp 0 lanes 0-15; pre-barrier)
    if (tid < 16) {
        const float* p = wq + tid * 3;     // gate ((app*2+l)*4+w)
        rot_mat_fast(p[0], p[1], p[2], qm[tid]);
    }

    float cg_, sg_;
    __sincosf(0.5f * pix, &sg_, &cg_);     // half-angle for amplitudes

    // broadcast all wires' c/s within the 4-lane group
    const float c0 = SH4(cg_, 0), s0 = SH4(sg_, 0);
    const float c1 = SH4(cg_, 1), s1 = SH4(sg_, 1);
    const float c2 = SH4(cg_, 2), s2 = SH4(sg_, 2);
    const float c3 = SH4(cg_, 3), s3 = SH4(sg_, 3);

    const int b1w = (g >> 1) & 1;          // wire0 bit
    const int b0w = g & 1;                 // wire1 bit

    // product state: amp(k) = prod_w (c_w or -i s_w); slot t = (wire2,wire3)
    const float f01  = (b1w ? s0 : c0) * (b0w ? s1 : c1);
    const int   popg = b1w + b0w;
    float ar0, ai0, ar1, ai1, ar2, ai2, ar3, ai3;
#define MK_AMP(T, W2, W3, AR, AI) {                                           \
        float mag = f01 * ((W2) ? s2 : c2) * ((W3) ? s3 : c3);                \
        int p_ = (popg + (W2) + (W3)) & 3;                                    \
        float sgn = (p_ & 2) ? -mag : mag;                                    \
        AR = (p_ & 1) ? 0.f : sgn;                                            \
        AI = (p_ & 1) ? -sgn : 0.f; }
    MK_AMP(0, 0, 0, ar0, ai0)
    MK_AMP(1, 0, 1, ar1, ai1)
    MK_AMP(2, 1, 0, ar2, ai2)
    MK_AMP(3, 1, 1, ar3, ai3)
#undef MK_AMP

    // ring-permutation source lanes (loop-invariant)
    const int La = (0x1320 >> (g << 2)) & 3;   // {0,2,3,1}[g]
    const int Lb = (0x2013 >> (g << 2)) & 3;   // {3,1,0,2}[g]
    const bool od = g & 1;

    __syncthreads();                       // b1: qm ready

    // start alpha/beta-independent work: gate phase
#pragma unroll
    for (int app = 0; app < 2; app++) {
        const int gbase = app * 8;
        // ----- layer l=0 (range 1) -----
        { const float4 mA = qm[gbase + 0][0], mB = qm[gbase + 0][1];
          ROT_CROSS(2, b1w, mA, mB) }
        { const float4 mA = qm[gbase + 1][0], mB = qm[gbase + 1][1];
          ROT_CROSS(1, b0w, mA, mB) }
        { const float4 mA = qm[gbase + 2][0], mB = qm[gbase + 2][1];
          ROT_LOCAL_PAIR(0, 2, mA, mB) ROT_LOCAL_PAIR(1, 3, mA, mB) }
        { const float4 mA = qm[gbase + 3][0], mB = qm[gbase + 3][1];
          ROT_LOCAL_PAIR(0, 1, mA, mB) ROT_LOCAL_PAIR(2, 3, mA, mB) }
        // merged CNOT ring r=1: one permutation stage
        { float x0r = SH4(ar0, La), x0i = SH4(ai0, La);
          float x3r = SH4(ar3, La), x3i = SH4(ai3, La);
          float x1r = SH4(ar1, Lb), x1i = SH4(ai1, Lb);
          float x2r = SH4(ar2, Lb), x2i = SH4(ai2, Lb);
          ar0 = od ? x2r : x0r; ai0 = od ? x2i : x0i;
          ar1 = od ? x3r : x1r; ai1 = od ? x3i : x1i;
          ar2 = od ? x1r : x3r; ai2 = od ? x1i : x3i;
          ar3 = od ? x0r : x2r; ai3 = od ? x0i : x2i; }

        // ----- layer l=1 (range 2) -----
        { const float4 mA = qm[gbase + 4][0], mB = qm[gbase + 4][1];
          ROT_CROSS(2, b1w, mA, mB) }
        { const float4 mA = qm[gbase + 5][0], mB = qm[gbase + 5][1];
          ROT_CROSS(1, b0w, mA, mB) }
        { const float4 mA = qm[gbase + 6][0], mB = qm[gbase + 6][1];
          ROT_LOCAL_PAIR(0, 2, mA, mB) ROT_LOCAL_PAIR(1, 3, mA, mB) }
        { const float4 mA = qm[gbase + 7][0], mB = qm[gbase + 7][1];
          ROT_LOCAL_PAIR(0, 1, mA, mB) ROT_LOCAL_PAIR(2, 3, mA, mB) }
        // merged CNOT ring r=2: dest t <- amp_g of lane g^t
        { float n0r = sel4(g,     ar0, ar1, ar2, ar3);
          float n0i = sel4(g,     ai0, ai1, ai2, ai3);
          float n1r = SH4X(sel4(g ^ 1, ar0, ar1, ar2, ar3), 1);
          float n1i = SH4X(sel4(g ^ 1, ai0, ai1, ai2, ai3), 1);
          float n2r = SH4X(sel4(g ^ 2, ar0, ar1, ar2, ar3), 2);
          float n2i = SH4X(sel4(g ^ 2, ai0, ai1, ai2, ai3), 2);
          float n3r = SH4X(sel4(g ^ 3, ar0, ar1, ar2, ar3), 3);
          float n3i = SH4X(sel4(g ^ 3, ai0, ai1, ai2, ai3), 3);
          ar0 = n0r; ai0 = n0i; ar1 = n1r; ai1 = n1i;
          ar2 = n2r; ai2 = n2i; ar3 = n3r; ai3 = n3i; }
    }

    // <Z_0>: sign by wire0 bit, reduce across the 4-lane group
    float part = ar0*ar0 + ai0*ai0 + ar1*ar1 + ai1*ai1
               + ar2*ar2 + ai2*ai2 + ar3*ar3 + ai3*ai3;
    part = b1w ? -part : part;
    part += SHX(part, 1);
    part += SHX(part, 2);
    const float ez = part;

    __syncthreads();                       // b2: alpha/beta + wo/bo ready

    float ce, sev;
    __sincosf(ez, &sev, &ce);
    const float q = ab[0] * ce + ab[1] * sev;

    // Linear(1,10) + log_softmax; exps split across the 4 lanes
    float lg[10];
#pragma unroll
    for (int k = 0; k < 10; k++) lg[k] = fmaf(q, wo[k], bo[k]);
    float pse = 0.f;
#pragma unroll
    for (int k = 0; k < 3; k++) {
        int idx = g + 4 * k;
        if (idx < 10) pse += __expf(lg[idx]);
    }
    pse += SHX(pse, 1);
    pse += SHX(pse, 2);
    const float off = __logf(pse);

    if (s < B) {
        float2* ob = (float2*)(out + (size_t)s * 10);   // 40B rows -> 8B aligned
        ob[g] = make_float2(lg[2 * g] - off, lg[2 * g + 1] - off);
        if (g == 0) ob[4] = make_float2(lg[8] - off, lg[9] - off);
    }
}

extern "C" void kernel_launch(void* const* d_in, const int* in_sizes, int n_in,
                              void* d_out, int out_size) {
    const float* x    = (const float*)d_in[0];   // [B,784]
    const float* wq   = (const float*)d_in[1];   // [2,2,4,3]
    const float* wfc  = (const float*)d_in[2];   // [3,3,1,3]
    const float* Wout = (const float*)d_in[3];   // [10,1]
    const float* bout = (const float*)d_in[4];   // [10]
    float* out = (float*)d_out;                  // [B,10]

    int B = in_sizes[0] / 784;
    int blocks = (B + 31) / 32;                  // 32 samples per block
    quanv_hybrid_kernel<<<blocks, 160>>>(x, wq, wfc, Wout, bout, out, B);
}

// round 8
// speedup vs baseline: 1.4952x; 1.0385x over previous
#include <cuda_runtime.h>
#include <math.h>

// QuanvolutionHybrid, reduced: only feats[:,0] (patch 0, wire0 <Z>) feeds the
// FC stage. Direct 4-qubit sim, 4 threads/sample, with ALL CNOT rings removed
// algebraically: rings are GF(2)-linear basis permutations, so they are
// commuted out of the circuit; each Rot becomes a two-level rotation on pairs
// (i, i^mu) with side parity sigma (mu = Q^-1 e_w, sigma = Q^T e_w, verified
// sigma.mu=1 for all 16 gates). Final permutation folds into the measurement
// mask, which comes out as wire0 again. Layout: lane bits = (wire0, wire3),
// slot bits = (wire1, wire2) -> 6/16 gates thread-local, 10 one-shfl-stage.

#define SHX(v, m) __shfl_xor_sync(0xffffffffu, (v), (m))
#define SH4(v, l) __shfl_sync(0xffffffffu, (v), (l), 4)

__device__ __forceinline__ void rot_mat_fast(float phi, float theta, float omega, float4* m) {
    // PennyLane Rot(phi,theta,omega) = RZ(omega) RY(theta) RZ(phi)
    float ct, st, ca, sa, cb, sb;
    __sincosf(0.5f * theta, &st, &ct);
    __sincosf(0.5f * (phi + omega), &sa, &ca);
    __sincosf(0.5f * (phi - omega), &sb, &cb);
    m[0] = make_float4( ct * ca, -ct * sa, -st * cb, -st * sb);  // m00, m01
    m[1] = make_float4( st * cb, -st * sb,  ct * ca,  ct * sa);  // m10, m11
}

// Generic conjugated two-level rotation.
//   GM = lane-xor mask (0..3), TM = slot-xor mask (0..3)
//   SG = sigma lane bits, ST = sigma slot bits; side(i) = parity(sigma & i)
#define GSLOT(T, GM, TM, SG, ST) {                                            \
    float apr = ar[(T) ^ (TM)], api = ai[(T) ^ (TM)];                         \
    if ((GM) != 0) { apr = SHX(apr, (GM)); api = SHX(api, (GM)); }            \
    const int side = pg ^ ((((ST) >> 1) & ((T) >> 1)) ^ ((ST) & (T) & 1));    \
    const float csr = side ? mB.z : mA.x, csi = side ? mB.w : mA.y;           \
    const float cpr = side ? mB.x : mA.z, cpi = side ? mB.y : mA.w;           \
    nr[T] = csr * ar[T] - csi * ai[T] + cpr * apr - cpi * api;                \
    ni[T] = csr * ai[T] + csi * ar[T] + cpr * api + cpi * apr; }

#define GGATE(GI, GM, TM, SG, ST) {                                           \
    const float4 mA = gm[GI][0], mB = gm[GI][1];                              \
    const int pg = (((SG) >> 1) & b1w) ^ ((SG) & b0w & 1);                    \
    float nr[4], ni[4];                                                       \
    GSLOT(0, GM, TM, SG, ST) GSLOT(1, GM, TM, SG, ST)                         \
    GSLOT(2, GM, TM, SG, ST) GSLOT(3, GM, TM, SG, ST)                         \
    ar[0] = nr[0]; ai[0] = ni[0]; ar[1] = nr[1]; ai[1] = ni[1];               \
    ar[2] = nr[2]; ai[2] = ni[2]; ar[3] = nr[3]; ai[3] = ni[3]; }

__global__ void __launch_bounds__(128)
quanv_hybrid_kernel(const float* __restrict__ x,
                    const float* __restrict__ wq,    // [2,2,4,3]
                    const float* __restrict__ wfc,   // [3,3,1,3]
                    const float* __restrict__ Wout,  // [10,1]
                    const float* __restrict__ bout,  // [10]
                    float* __restrict__ out,         // [B,10]
                    int B)
{
    __shared__ float4 gm[25][2];   // [0..15] quanv gates, [16..24] fc gates
    __shared__ float  wob[20];     // wo[0..9], bo[0..9]

    const int tid = threadIdx.x;
    const int g   = tid & 3;
    const int s   = blockIdx.x * 32 + (tid >> 2);
    const int scl = (s < B) ? s : (B - 1);

    // Sample pixel load first (cold DRAM overlaps prologue). Lane g loads
    // wire-g angle: patch 0 offsets {0,1,28,29}.
    const float pix = x[(size_t)scl * 784 + ((g & 1) + 28 * (g >> 1))];

    // ---- branchless prologue: all 25 Rot matrices + head weights ----
    if (tid < 25) {
        const float* p = (tid < 16) ? (wq + tid * 3) : (wfc + (tid - 16) * 3);
        rot_mat_fast(p[0], p[1], p[2], gm[tid]);
    } else if (tid >= 32 && tid < 52) {
        const int l = tid - 32;
        wob[l] = __ldg((l < 10) ? (Wout + l) : (bout + (l - 10)));
    }

    float cg_, sg_;
    __sincosf(0.5f * pix, &sg_, &cg_);
    const float c0 = SH4(cg_, 0), s0 = SH4(sg_, 0);
    const float c1 = SH4(cg_, 1), s1 = SH4(sg_, 1);
    const float c2 = SH4(cg_, 2), s2 = SH4(sg_, 2);
    const float c3 = SH4(cg_, 3), s3 = SH4(sg_, 3);

    // Layout: lane bits (b1w,b0w) = (wire0,wire3); slot bits = (wire1,wire2)
    const int b1w = (g >> 1) & 1;
    const int b0w = g & 1;

    // RX product state: amp = (-i)^pops * prod(c or s per wire bit)
    float ar[4], ai[4];
    {
        const float fl = (b1w ? s0 : c0) * (b0w ? s3 : c3);
#define MKAMP(T) {                                                            \
        const int tb1 = (T) >> 1, tb0 = (T) & 1;                              \
        float mag = fl * (tb1 ? s1 : c1) * (tb0 ? s2 : c2);                   \
        int p_ = (b1w + b0w + tb1 + tb0) & 3;                                 \
        float sv = (p_ & 2) ? -mag : mag;                                     \
        ar[T] = (p_ & 1) ? 0.f : sv;                                          \
        ai[T] = (p_ & 1) ? -sv : 0.f; }
        MKAMP(0) MKAMP(1) MKAMP(2) MKAMP(3)
#undef MKAMP
    }

    __syncthreads();   // gate matrices + wob ready

    // ---- 16 conjugated rotations (rings eliminated; masks derived offline,
    //      sigma.mu = 1 verified for every gate) ----
    GGATE( 0, 2, 0, 2, 0)   // L0 w0
    GGATE( 1, 0, 2, 0, 2)   // L0 w1
    GGATE( 2, 0, 1, 0, 1)   // L0 w2
    GGATE( 3, 1, 0, 1, 0)   // L0 w3
    GGATE( 4, 2, 2, 1, 3)   // L1 w0   (mu=12, sg=7)
    GGATE( 5, 0, 3, 2, 2)   // L1 w1   (mu=6,  sg=12)
    GGATE( 6, 1, 1, 2, 3)   // L1 w2   (mu=3,  sg=14)
    GGATE( 7, 3, 2, 3, 3)   // L1 w3   (mu=13, sg=15)
    GGATE( 8, 3, 3, 2, 3)   // L2 w0   (mu=15, sg=14)
    GGATE( 9, 3, 1, 3, 3)   // L2 w1   (mu=11, sg=15)
    GGATE(10, 2, 2, 3, 0)   // L2 w2   (mu=12, sg=9)
    GGATE(11, 0, 3, 1, 1)   // L2 w3   (mu=6,  sg=3)
    GGATE(12, 0, 2, 1, 2)   // L3 w0   (mu=4,  sg=5)
    GGATE(13, 1, 3, 1, 0)   // L3 w1   (mu=7,  sg=1)
    GGATE(14, 2, 1, 2, 0)   // L3 w2   (mu=10, sg=8)
    GGATE(15, 0, 1, 3, 1)   // L3 w3   (mu=2,  sg=11)

    // ---- <Z>: final perm folds to mask = wire0 = lane bit b1w ----
    float part = ar[0]*ar[0] + ai[0]*ai[0] + ar[1]*ar[1] + ai[1]*ai[1]
               + ar[2]*ar[2] + ai[2]*ai[2] + ar[3]*ar[3] + ai[3]*ai[3];
    part = b1w ? -part : part;
    part += SHX(part, 1);
    part += SHX(part, 2);
    const float ez = part;

    // ---- 1-qubit FC circuit: RX(ez)|0>, then 9 shared Rot gates ----
    float cf, sf;
    __sincosf(0.5f * ez, &sf, &cf);
    float a0r = cf, a0i = 0.f, a1r = 0.f, a1i = -sf;
#pragma unroll
    for (int gi = 16; gi < 25; gi++) {
        const float4 mA = gm[gi][0];
        const float4 mB = gm[gi][1];
        float n0r = mA.x*a0r - mA.y*a0i + mA.z*a1r - mA.w*a1i;
        float n0i = mA.x*a0i + mA.y*a0r + mA.z*a1i + mA.w*a1r;
        float n1r = mB.x*a0r - mB.y*a0i + mB.z*a1r - mB.w*a1i;
        float n1i = mB.x*a0i + mB.y*a0r + mB.z*a1i + mB.w*a1r;
        a0r = n0r; a0i = n0i; a1r = n1r; a1i = n1i;
    }
    const float q = (a0r*a0r + a0i*a0i) - (a1r*a1r + a1i*a1i);

    // ---- Linear(1,10) + log_softmax; exps split across the 4 lanes ----
    float lg[10];
#pragma unroll
    for (int k = 0; k < 10; k++) lg[k] = fmaf(q, wob[k], wob[10 + k]);
    float pse = 0.f;
#pragma unroll
    for (int k = 0; k < 3; k++) {
        int idx = g + 4 * k;
        if (idx < 10) pse += __expf(lg[idx]);
    }
    pse += SHX(pse, 1);
    pse += SHX(pse, 2);
    const float off = __logf(pse);

    if (s < B) {
        float2* ob = (float2*)(out + (size_t)s * 10);   // 40B rows, 8B aligned
        ob[g] = make_float2(lg[2 * g] - off, lg[2 * g + 1] - off);
        if (g == 0) ob[4] = make_float2(lg[8] - off, lg[9] - off);
    }
}

extern "C" void kernel_launch(void* const* d_in, const int* in_sizes, int n_in,
                              void* d_out, int out_size) {
    const float* x    = (const float*)d_in[0];   // [B,784]
    const float* wq   = (const float*)d_in[1];   // [2,2,4,3]
    const float* wfc  = (const float*)d_in[2];   // [3,3,1,3]
    const float* Wout = (const float*)d_in[3];   // [10,1]
    const float* bout = (const float*)d_in[4];   // [10]
    float* out = (float*)d_out;                  // [B,10]

    int B = in_sizes[0] / 784;
    int blocks = (B + 31) / 32;                  // 32 samples per 128-thread block
    quanv_hybrid_kernel<<<blocks, 128>>>(x, wq, wfc, Wout, bout, out, B);
}